// round 2
// baseline (speedup 1.0000x reference)
#include <cuda_runtime.h>
#include <cuda_bf16.h>
#include <cstdint>

// VoxelPooler: scatter-add point features into a dense BEV grid.
// geometry [B,N,D,H,W,3] f32, features [B,N,D,H,W,64] f32
// output   [B, Z*C, X, Y] f32 with Z=8, C=64, X=200, Y=200
//
// Strategy:
//   - Process one batch at a time: zero its 82MB output slab, then scatter.
//     82MB < 126MB L2, so the atomic read-modify-writes hit L2-resident zeros
//     and each output byte goes to DRAM exactly once (the final writeback).
//   - Warp per point: lane l handles channels l and l+32 -> two coalesced
//     128B feature loads per warp; 2 spread-address REDG.F32 per lane.

constexpr int GX = 200;
constexpr int GY = 200;
constexpr int GZ = 8;
constexpr int CH = 64;
constexpr int XY = GX * GY;
constexpr int NB = 4;
constexpr int PPB = 6 * 41 * 16 * 44;      // 173184 points per batch
constexpr long long OUT_PER_B = (long long)GZ * CH * XY;  // 20,480,000 floats

__global__ void vp_zero_kernel(float4* __restrict__ out, int n4) {
    int i = blockIdx.x * blockDim.x + threadIdx.x;
    int stride = gridDim.x * blockDim.x;
    float4 z = make_float4(0.f, 0.f, 0.f, 0.f);
    for (; i < n4; i += stride) out[i] = z;
}

__global__ void __launch_bounds__(256) vp_scatter_kernel(
    const float* __restrict__ geo,
    const float* __restrict__ feat,
    const float* __restrict__ vsize,
    const float* __restrict__ vorig,
    float* __restrict__ out,
    int b)
{
    int gtid = blockIdx.x * blockDim.x + threadIdx.x;
    int p    = gtid >> 5;          // warp index = point within batch
    int lane = gtid & 31;
    if (p >= PPB) return;

    long long pidx = (long long)b * PPB + p;

    const float* g = geo + pidx * 3;
    float px = g[0], py = g[1], pz = g[2];

    // fp32 ops matching jnp exactly; __fdiv_rn resists fast-math rewrites.
    float ox = __ldg(&vorig[0]), oy = __ldg(&vorig[1]), oz = __ldg(&vorig[2]);
    float vx = __ldg(&vsize[0]), vy = __ldg(&vsize[1]), vz = __ldg(&vsize[2]);

    int ix = (int)floorf(__fdiv_rn(px - ox, vx));
    int iy = (int)floorf(__fdiv_rn(py - oy, vy));
    int iz = (int)floorf(__fdiv_rn(pz - oz, vz));

    if ((unsigned)ix >= (unsigned)GX ||
        (unsigned)iy >= (unsigned)GY ||
        (unsigned)iz >= (unsigned)GZ) return;   // ref scatters zeros: no-op

    const float* f = feat + pidx * (long long)CH;
    float f0 = f[lane];
    float f1 = f[lane + 32];

    // out[((b*GZ + iz)*CH + c)*XY + ix*GY + iy]
    long long base = ((long long)(b * GZ + iz) * CH) * XY + (long long)ix * GY + iy;
    atomicAdd(out + base + (long long)lane * XY, f0);
    atomicAdd(out + base + (long long)(lane + 32) * XY, f1);
}

extern "C" void kernel_launch(void* const* d_in, const int* in_sizes, int n_in,
                              void* d_out, int out_size)
{
    const float* geo   = (const float*)d_in[0];  // [B,N,D,H,W,3]
    const float* feat  = (const float*)d_in[1];  // [B,N,D,H,W,64]
    const float* vsize = (const float*)d_in[2];  // [3]
    const float* vorig = (const float*)d_in[3];  // [3]
    float* out = (float*)d_out;

    const int n4_per_b = (int)(OUT_PER_B / 4);             // 5,120,000 float4
    const int zero_blocks = 2048;
    const int scatter_threads = PPB * 32;                  // warp per point
    const int scatter_blocks = (scatter_threads + 255) / 256;

    for (int b = 0; b < NB; ++b) {
        float4* out_b = (float4*)(out + (long long)b * OUT_PER_B);
        vp_zero_kernel<<<zero_blocks, 256>>>(out_b, n4_per_b);
        vp_scatter_kernel<<<scatter_blocks, 256>>>(geo, feat, vsize, vorig, out, b);
    }
}

// round 3
// speedup vs baseline: 1.6029x; 1.6029x over previous
#include <cuda_runtime.h>
#include <cuda_bf16.h>
#include <cstdint>

// VoxelPooler via counting-sort + per-row smem pooling.
// geometry [B,N,D,H,W,3] f32, features [B,N,D,H,W,64] f32
// output   [B, Z*C, X, Y] f32, Z=8 C=64 X=200 Y=200
//
// Rows = (b, z, x): 4*8*200 = 6400. Each output row is 64ch x 200y = 51KB,
// pooled in shared memory (padded stride 201 -> conflict-free smem atomics),
// then streamed to gmem with float4 stores. No global atomics on the output,
// no separate zero pass: every output byte is written exactly once.

constexpr int GX = 200;
constexpr int GY = 200;
constexpr int GZ = 8;
constexpr int CH = 64;
constexpr int XY = GX * GY;
constexpr int NB = 4;
constexpr int PPB  = 6 * 41 * 16 * 44;     // 173184 points per batch
constexpr int PTOT = NB * PPB;             // 692736
constexpr int NROWS = NB * GZ * GX;        // 6400
constexpr int PADY = GY + 1;               // 201 (bank stride 9, coprime 32)

// Scratch (device globals: allocation-free rule)
__device__ int      d_count[NROWS];
__device__ int      d_offset[NROWS + 1];
__device__ int      d_cursor[NROWS];
__device__ int      d_pvox[PTOT];          // (row<<8)|y, or -1 invalid
__device__ unsigned d_plist[PTOT];         // (p<<8)|y, grouped by row

__global__ void vp_zero_count() {
    int i = blockIdx.x * blockDim.x + threadIdx.x;
    if (i < NROWS) d_count[i] = 0;
}

__global__ void __launch_bounds__(256) vp_bin_count(
    const float* __restrict__ geo,
    const float* __restrict__ vsize,
    const float* __restrict__ vorig)
{
    int p = blockIdx.x * blockDim.x + threadIdx.x;
    if (p >= PTOT) return;

    const float* g = geo + (size_t)p * 3;
    float px = g[0], py = g[1], pz = g[2];

    // exact fp32 semantics matching jnp: sub (rn), div (rn), floorf, int cast
    int ix = (int)floorf(__fdiv_rn(px - __ldg(&vorig[0]), __ldg(&vsize[0])));
    int iy = (int)floorf(__fdiv_rn(py - __ldg(&vorig[1]), __ldg(&vsize[1])));
    int iz = (int)floorf(__fdiv_rn(pz - __ldg(&vorig[2]), __ldg(&vsize[2])));

    if ((unsigned)ix >= (unsigned)GX ||
        (unsigned)iy >= (unsigned)GY ||
        (unsigned)iz >= (unsigned)GZ) { d_pvox[p] = -1; return; }

    int b = p / PPB;
    int row = (b * GZ + iz) * GX + ix;
    d_pvox[p] = (row << 8) | iy;
    atomicAdd(&d_count[row], 1);
}

// Exclusive scan of 6400 counts; also seeds cursors. One block.
__global__ void __launch_bounds__(1024) vp_scan() {
    __shared__ int partial[1024];
    const int CHK = (NROWS + 1023) / 1024;   // 7
    int t = threadIdx.x;
    int base = t * CHK;
    int vals[CHK];
    int s = 0;
    #pragma unroll
    for (int k = 0; k < CHK; ++k) {
        int idx = base + k;
        int v = (idx < NROWS) ? d_count[idx] : 0;
        vals[k] = s;            // local exclusive prefix
        s += v;
    }
    partial[t] = s;
    __syncthreads();
    if (t == 0) {
        int run = 0;
        for (int i = 0; i < 1024; ++i) { int tmp = partial[i]; partial[i] = run; run += tmp; }
        d_offset[NROWS] = run;
    }
    __syncthreads();
    int off = partial[t];
    #pragma unroll
    for (int k = 0; k < CHK; ++k) {
        int idx = base + k;
        if (idx < NROWS) {
            int o = off + vals[k];
            d_offset[idx] = o;
            d_cursor[idx] = o;
        }
    }
}

__global__ void __launch_bounds__(256) vp_fill() {
    int p = blockIdx.x * blockDim.x + threadIdx.x;
    if (p >= PTOT) return;
    int v = d_pvox[p];
    if (v < 0) return;
    int row = v >> 8;
    int pos = atomicAdd(&d_cursor[row], 1);
    d_plist[pos] = ((unsigned)p << 8) | (unsigned)(v & 255);
}

// One CTA per (b,z,x) row: pool into padded smem tile, stream out.
__global__ void __launch_bounds__(256) vp_rowpool(
    const float* __restrict__ feat,
    float* __restrict__ out)
{
    __shared__ float acc[CH * PADY];   // 64*201*4 = 51456 B

    int r = blockIdx.x;
    for (int i = threadIdx.x; i < CH * PADY; i += 256) acc[i] = 0.0f;
    __syncthreads();

    int s0 = d_offset[r], s1 = d_offset[r + 1];
    int warp = threadIdx.x >> 5, lane = threadIdx.x & 31;

    for (int i = s0 + warp; i < s1; i += 8) {
        unsigned e = d_plist[i];
        int y = (int)(e & 255u);
        size_t p = (size_t)(e >> 8);
        const float* f = feat + p * CH;
        float f0 = f[lane];
        float f1 = f[lane + 32];
        atomicAdd(&acc[lane * PADY + y], f0);          // banks (9*lane+y)%32: conflict-free
        atomicAdd(&acc[(lane + 32) * PADY + y], f1);
    }
    __syncthreads();

    int b = r / (GZ * GX);
    int zx = r % (GZ * GX);
    int z = zx / GX, x = zx % GX;
    float* ob = out + ((size_t)(b * GZ + z) * CH) * XY + (size_t)x * GY;

    // 64 ch * 50 float4 = 3200 vector stores, coalesced.
    for (int i = threadIdx.x; i < CH * (GY / 4); i += 256) {
        int c  = i / (GY / 4);
        int y4 = (i % (GY / 4)) * 4;
        const float* a = &acc[c * PADY + y4];
        float4 v = make_float4(a[0], a[1], a[2], a[3]);
        *reinterpret_cast<float4*>(ob + (size_t)c * XY + y4) = v;
    }
}

extern "C" void kernel_launch(void* const* d_in, const int* in_sizes, int n_in,
                              void* d_out, int out_size)
{
    const float* geo   = (const float*)d_in[0];
    const float* feat  = (const float*)d_in[1];
    const float* vsize = (const float*)d_in[2];
    const float* vorig = (const float*)d_in[3];
    float* out = (float*)d_out;

    vp_zero_count<<<(NROWS + 255) / 256, 256>>>();
    vp_bin_count<<<(PTOT + 255) / 256, 256>>>(geo, vsize, vorig);
    vp_scan<<<1, 1024>>>();
    vp_fill<<<(PTOT + 255) / 256, 256>>>();
    vp_rowpool<<<NROWS, 256>>>(feat, out);
}